// round 13
// baseline (speedup 1.0000x reference)
#include <cuda_runtime.h>
#include <stdint.h>

#define SEQ   8192
#define DKE   64
#define QT    128          // query rows per CTA
#define KT    64           // keys per tile
#define CHUNK 1024         // keys per split-K chunk
#define NQT   (SEQ/QT)     // 64
#define MAXC  (SEQ/CHUNK)  // 8
#define CPT   (CHUNK/QT)   // 8
#define WROWS 16           // q rows per warp
#define NTILE (SEQ/KT)     // 128 key tiles
#define TWK   2048         // uint32 words per K tile (f16x2)
#define TWV   2048         // uint32 words per V tile (f16x2)

// scratch (__device__ globals; no allocation). Zero-init (.bss) at load.
__device__ float    g_pout[MAXC][SEQ][DKE];  // unnormalized partial O
__device__ float    g_pl[MAXC][SEQ];         // partial row sum
__device__ uint32_t g_kh[NTILE][TWK];        // K tiles, f16, fragment-major
__device__ uint32_t g_vh[NTILE][TWV];        // V tiles, f16, fragment-major

__device__ __forceinline__ uint32_t f16x2(float hi, float lo) {
    uint32_t r;
    asm("cvt.rn.f16x2.f32 %0, %1, %2;" : "=r"(r) : "f"(hi), "f"(lo));
    return r;
}
__device__ __forceinline__ uint32_t hmul2(uint32_t a, uint32_t b) {
    uint32_t r;
    asm("mul.f16x2 %0, %1, %2;" : "=r"(r) : "r"(a), "r"(b));
    return r;
}
__device__ __forceinline__ uint32_t hex2(uint32_t a) {
    uint32_t r;
    asm("ex2.approx.f16x2 %0, %1;" : "=r"(r) : "r"(a));
    return r;
}
__device__ __forceinline__ void mma_f16(float c[4], const uint32_t a[4],
                                        uint32_t b0, uint32_t b1) {
    asm("mma.sync.aligned.m16n8k16.row.col.f32.f16.f16.f32 "
        "{%0,%1,%2,%3}, {%4,%5,%6,%7}, {%8,%9}, {%0,%1,%2,%3};"
        : "+f"(c[0]), "+f"(c[1]), "+f"(c[2]), "+f"(c[3])
        : "r"(a[0]), "r"(a[1]), "r"(a[2]), "r"(a[3]), "r"(b0), "r"(b1));
}
__device__ __forceinline__ void cp16(uint32_t saddr, const void* g) {
    asm volatile("cp.async.cg.shared.global [%0], [%1], 16;"
                 :: "r"(saddr), "l"(g));
}
#define CP_COMMIT() asm volatile("cp.async.commit_group;")
#define CP_WAIT1()  asm volatile("cp.async.wait_group 1;")
#define CP_WAIT0()  asm volatile("cp.async.wait_group 0;")

// score scale: 1/64 (problem scale) * log2(e), applied post-MMA (f16x2 domain)
#define SSCALE (0.015625f * 1.44269504088896340736f)

// ---- prep: K,V -> f16x2 fragment-major tile blocks (m16n8k16 layouts) ----
// grid = NTILE*4; balanced: warps 0-3 do 2 K-float4s/thread,
// warps 4-7 do 1 V pair-item/thread (~equal cost).
__global__ __launch_bounds__(256)
void prep_kv(const float* __restrict__ k, const float* __restrict__ v) {
    const int tile = blockIdx.x >> 2;
    const int quad = blockIdx.x & 3;
    const int tid  = threadIdx.x;
    const float4* kg = (const float4*)(k + (size_t)tile * KT * DKE);
    const float4* vg = (const float4*)(v + (size_t)tile * KT * DKE);
    uint32_t* kd = g_kh[tile];
    uint32_t* vd = g_vh[tile];

    if (tid < 128) {
        // --- K: 2 float4s per thread ---
        #pragma unroll
        for (int u = 0; u < 2; u++) {
            int idx = quad * 256 + tid * 2 + u;   // float4 index 0..1023
            int r   = idx >> 4;                   // key row in tile
            int c0  = (idx & 15) << 2;            // dim base
            float4 x = kg[idx];
            int nb  = r >> 3, gg = r & 7;
            int k16 = c0 >> 4, k16p = k16 >> 1;
            int b   = (c0 >> 3) & 1;
            int w   = 2 * (k16 & 1) + b;
            int t0  = (c0 & 7) >> 1;              // 0 or 2
            uint32_t* base = kd + ((nb * 2 + k16p) * 32 + gg * 4) * 4;
            base[t0 * 4 + w]       = f16x2(x.y, x.x);
            base[(t0 + 1) * 4 + w] = f16x2(x.w, x.z);
        }
    } else {
        // --- V: 1 key-pair item per thread ---
        int pi = quad * 128 + (tid - 128);        // pair index 0..511
        int r0 = (pi >> 4) * 2;                   // even key
        int c0 = (pi & 15) * 4;                   // dim base
        float4 v0 = vg[r0 * (DKE / 4) + (c0 >> 2)];
        float4 v1 = vg[(r0 + 1) * (DKE / 4) + (c0 >> 2)];
        int k16 = r0 >> 4;
        int p16 = r0 & 15;
        int b   = p16 >> 3;
        int tt  = (p16 & 7) >> 1;
        int nb  = c0 >> 3, nbp = nb >> 1;
        int w   = b + 2 * (nb & 1);
        int g0  = c0 & 7;
        uint32_t* base = vd + ((k16 * 4 + nbp) * 32) * 4;
        base[(g0 + 0) * 16 + tt * 4 + w] = f16x2(v1.x, v0.x);
        base[(g0 + 1) * 16 + tt * 4 + w] = f16x2(v1.y, v0.y);
        base[(g0 + 2) * 16 + tt * 4 + w] = f16x2(v1.z, v0.z);
        base[(g0 + 3) * 16 + tt * 4 + w] = f16x2(v1.w, v0.w);
    }
}

__global__ __launch_bounds__(256, 2)
void attn_phase1(const float* __restrict__ q) {
    const int m = blockIdx.y;
    const int c = blockIdx.x;
    if (c > m / CPT) return;

    __shared__ uint32_t ksf[2][TWK];   // 16 KB, K double buffer
    __shared__ uint32_t vsf[TWV];      //  8 KB, V single buffer

    const int tid  = threadIdx.x;
    const int w    = tid >> 5;
    const int lane = tid & 31;
    const int g    = lane >> 2;
    const int t    = lane & 3;
    const int row_base = m * QT + w * WROWS;
    const int row0 = row_base + g;
    const int row1 = row0 + 8;

    const uint32_t ksb = (uint32_t)__cvta_generic_to_shared(&ksf[0][0]);
    const uint32_t vsb = (uint32_t)__cvta_generic_to_shared(vsf);

    const int kstart = c * CHUNK;
    const int kend   = min(kstart + CHUNK, (m + 1) * QT);
    const int ntiles = (kend - kstart) / KT;
    const int tile0  = kstart / KT;

    // ---- prologue: start K(0) copy, then build Q frags while it flies ----
    {
        const uint4* ksrc = (const uint4*)g_kh[tile0];
        #pragma unroll
        for (int j = 0; j < 2; j++) {
            int o4 = tid + j * 256;
            cp16(ksb + o4 * 16, ksrc + o4);
        }
    }
    CP_COMMIT();

    // ---- Q fragments (raw fp16; scale applied post-MMA) ----
    uint32_t qA[4][4];
    #pragma unroll
    for (int k16 = 0; k16 < 4; k16++) {
        const float* q0 = q + (size_t)row0 * DKE + k16 * 16;
        const float* q1 = q + (size_t)row1 * DKE + k16 * 16;
        qA[k16][0] = f16x2(q0[2 * t + 1], q0[2 * t]);
        qA[k16][1] = f16x2(q1[2 * t + 1], q1[2 * t]);
        qA[k16][2] = f16x2(q0[2 * t + 9], q0[2 * t + 8]);
        qA[k16][3] = f16x2(q1[2 * t + 9], q1[2 * t + 8]);
    }

    const uint32_t sc2  = f16x2(SSCALE, SSCALE);
    const uint32_t ones = (g == 0) ? 0x3C003C00u : 0u;   // ones-column B frag

    float o[8][4];
    #pragma unroll
    for (int nb = 0; nb < 8; nb++)
        o[nb][0] = o[nb][1] = o[nb][2] = o[nb][3] = 0.f;
    float ol[4] = {0.f, 0.f, 0.f, 0.f};   // l accumulator (tensor-core sum)

    uint32_t pP[8][2];   // packed p: pP[nb] = { {p1,p0}, {p3,p2} }

    for (int i = 0; i < ntiles; i++) {
        CP_WAIT0();          // my K(i) done (only pending group)
        __syncthreads();     // B1: everyone's K(i) visible; buffers reusable

        // issue V(i)  [consumed after B2 -> gets the QK+softmax window]
        {
            const uint4* vsrc = (const uint4*)g_vh[tile0 + i];
            #pragma unroll
            for (int j = 0; j < 2; j++) {
                int o4 = tid + j * 256;
                cp16(vsb + o4 * 16, vsrc + o4);
            }
        }
        CP_COMMIT();
        // issue K(i+1) into the other K buffer (whole-tile window)
        if (i + 1 < ntiles) {
            const uint4* ksrc = (const uint4*)g_kh[tile0 + i + 1];
            uint32_t kb = ksb + ((i + 1) & 1) * (TWK * 4);
            #pragma unroll
            for (int j = 0; j < 2; j++) {
                int o4 = tid + j * 256;
                cp16(kb + o4 * 16, ksrc + o4);
            }
        }
        CP_COMMIT();         // (empty group at last tile keeps counts uniform)

        const int kt = kstart + i * KT;
        const bool active = (kt <= row_base + WROWS - 1);  // warp-uniform
        const uint32_t* kbuf = ksf[i & 1];

        if (active) {
            // ---- S = Q K^T (fp16 m16n8k16, fp32 accum) ----
            float s[8][4];
            #pragma unroll
            for (int nb = 0; nb < 8; nb++)
                s[nb][0] = s[nb][1] = s[nb][2] = s[nb][3] = 0.f;
            #pragma unroll
            for (int nb = 0; nb < 8; nb++) {
                #pragma unroll
                for (int kp = 0; kp < 2; kp++) {
                    uint4 b = *(const uint4*)&kbuf[((nb * 2 + kp) * 32 + lane) * 4];
                    mma_f16(s[nb], qA[2 * kp],     b.x, b.y);
                    mma_f16(s[nb], qA[2 * kp + 1], b.z, b.w);
                }
            }

            // ---- mask (fp32) + packed f16x2 softmax: p = 2^(s*SC) ----
            const bool diag = (kt + KT - 1 > row_base);
            #pragma unroll
            for (int nb = 0; nb < 8; nb++) {
                float t0 = s[nb][0], t1 = s[nb][1];
                float t2 = s[nb][2], t3 = s[nb][3];
                if (diag) {
                    int j0 = kt + nb * 8 + 2 * t;
                    int j1 = j0 + 1;
                    if (j0 > row0) t0 = -1e30f;   // -> f16 -inf -> p = 0
                    if (j1 > row0) t1 = -1e30f;
                    if (j0 > row1) t2 = -1e30f;
                    if (j1 > row1) t3 = -1e30f;
                }
                pP[nb][0] = hex2(hmul2(f16x2(t1, t0), sc2));
                pP[nb][1] = hex2(hmul2(f16x2(t3, t2), sc2));
            }
        }

        CP_WAIT1();          // my V(i) done (K(i+1) may still be in flight)
        __syncthreads();     // B2: everyone's V(i) visible

        if (active) {
            // ---- O += P V ; l += P * ones (constant-register B frag) ----
            #pragma unroll
            for (int k16 = 0; k16 < 4; k16++) {
                uint32_t pA[4];
                pA[0] = pP[2 * k16][0];
                pA[1] = pP[2 * k16][1];
                pA[2] = pP[2 * k16 + 1][0];
                pA[3] = pP[2 * k16 + 1][1];
                #pragma unroll
                for (int nbp = 0; nbp < 4; nbp++) {
                    uint4 b = *(const uint4*)&vsf[((k16 * 4 + nbp) * 32 + lane) * 4];
                    mma_f16(o[2 * nbp],     pA, b.x, b.y);
                    mma_f16(o[2 * nbp + 1], pA, b.z, b.w);
                }
                mma_f16(ol, pA, ones, ones);   // col 0 = row sum of p
            }
        }
    }
    CP_WAIT0();   // drain tail groups

    // ---- write split-K partials (l lives in t==0's col-0 accumulators) ----
    #pragma unroll
    for (int nb = 0; nb < 8; nb++) {
        *(float2*)&g_pout[c][row0][nb * 8 + 2 * t] = make_float2(o[nb][0], o[nb][1]);
        *(float2*)&g_pout[c][row1][nb * 8 + 2 * t] = make_float2(o[nb][2], o[nb][3]);
    }
    if (t == 0) {
        g_pl[c][row0] = ol[0];
        g_pl[c][row1] = ol[2];
    }
}

// Combine: one thread per (row, 4-dim quarter); <=8 predicated independent
// LDG.128 + broadcast denom loads. grid = SEQ*16/256 = 512.
__global__ __launch_bounds__(256)
void attn_phase2(float* __restrict__ out) {
    const int tid = blockIdx.x * 256 + threadIdx.x;
    const int row = tid >> 4;
    const int qt  = tid & 15;
    const int nch = row / CHUNK + 1;

    float denom = 0.f;
    float4 o = make_float4(0.f, 0.f, 0.f, 0.f);
    #pragma unroll
    for (int c = 0; c < MAXC; c++) {
        if (c < nch) {
            denom += g_pl[c][row];
            float4 x = *(const float4*)&g_pout[c][row][qt * 4];
            o.x += x.x; o.y += x.y; o.z += x.z; o.w += x.w;
        }
    }
    float inv = 1.0f / denom;
    *(float4*)&out[(size_t)row * DKE + qt * 4] =
        make_float4(o.x * inv, o.y * inv, o.z * inv, o.w * inv);
}

extern "C" void kernel_launch(void* const* d_in, const int* in_sizes, int n_in,
                              void* d_out, int out_size) {
    const float* q = (const float*)d_in[0];
    const float* k = (const float*)d_in[1];
    const float* v = (const float*)d_in[2];
    float* out = (float*)d_out;

    prep_kv<<<NTILE * 4, 256>>>(k, v);
    dim3 grid1(MAXC, NQT);
    attn_phase1<<<grid1, 256>>>(q);
    attn_phase2<<<SEQ * 16 / 256, 256>>>(out);
}

// round 14
// speedup vs baseline: 1.4856x; 1.4856x over previous
#include <cuda_runtime.h>
#include <stdint.h>

#define SEQ   8192
#define DKE   64
#define QT    128          // query rows per CTA
#define KT    64           // keys per tile
#define CHUNK 1024         // keys per split-K chunk
#define NQT   (SEQ/QT)     // 64
#define MAXC  (SEQ/CHUNK)  // 8
#define CPT   (CHUNK/QT)   // 8
#define WROWS 16           // q rows per warp
#define NTILE (SEQ/KT)     // 128 key tiles
#define TWK   2048         // uint32 words per K tile (f16x2)
#define TWV   2048         // uint32 words per V tile (f16x2)
#define TILEB (TWK*4)      // 8192 bytes per tile block

// scratch (__device__ globals; no allocation). Zero-init (.bss) at load.
__device__ float    g_pout[MAXC][SEQ][DKE];  // unnormalized partial O
__device__ float    g_pl[MAXC][SEQ];         // partial row sum
__device__ uint32_t g_kh[NTILE][TWK];        // K tiles, f16, fragment-major
__device__ uint32_t g_vh[NTILE][TWV];        // V tiles, f16, fragment-major

__device__ __forceinline__ uint32_t f16x2(float hi, float lo) {
    uint32_t r;
    asm("cvt.rn.f16x2.f32 %0, %1, %2;" : "=r"(r) : "f"(hi), "f"(lo));
    return r;
}
__device__ __forceinline__ uint32_t hmul2(uint32_t a, uint32_t b) {
    uint32_t r;
    asm("mul.f16x2 %0, %1, %2;" : "=r"(r) : "r"(a), "r"(b));
    return r;
}
__device__ __forceinline__ uint32_t hex2(uint32_t a) {
    uint32_t r;
    asm("ex2.approx.f16x2 %0, %1;" : "=r"(r) : "r"(a));
    return r;
}
__device__ __forceinline__ void mma_f16(float c[4], const uint32_t a[4],
                                        uint32_t b0, uint32_t b1) {
    asm("mma.sync.aligned.m16n8k16.row.col.f32.f16.f16.f32 "
        "{%0,%1,%2,%3}, {%4,%5,%6,%7}, {%8,%9}, {%0,%1,%2,%3};"
        : "+f"(c[0]), "+f"(c[1]), "+f"(c[2]), "+f"(c[3])
        : "r"(a[0]), "r"(a[1]), "r"(a[2]), "r"(a[3]), "r"(b0), "r"(b1));
}
// ---- bulk async copy (TMA/UBLKCP) + mbarrier ----
__device__ __forceinline__ void mbar_init(uint32_t addr, uint32_t count) {
    asm volatile("mbarrier.init.shared.b64 [%0], %1;" :: "r"(addr), "r"(count) : "memory");
}
__device__ __forceinline__ void mbar_expect(uint32_t addr, uint32_t bytes) {
    asm volatile("mbarrier.arrive.expect_tx.shared.b64 _, [%0], %1;"
                 :: "r"(addr), "r"(bytes) : "memory");
}
__device__ __forceinline__ void mbar_wait(uint32_t addr, uint32_t parity) {
    asm volatile(
        "{\n\t.reg .pred P;\n\t"
        "W_%=:\n\t"
        "mbarrier.try_wait.parity.acquire.cta.shared::cta.b64 P, [%0], %1, 0x989680;\n\t"
        "@!P bra W_%=;\n\t}"
        :: "r"(addr), "r"(parity) : "memory");
}
__device__ __forceinline__ void bulk_cp(uint32_t sdst, const void* gsrc,
                                        uint32_t bytes, uint32_t mbar) {
    asm volatile(
        "cp.async.bulk.shared::cta.global.mbarrier::complete_tx::bytes [%0], [%1], %2, [%3];"
        :: "r"(sdst), "l"(gsrc), "r"(bytes), "r"(mbar) : "memory");
}

// score scale: 1/64 (problem scale) * log2(e), applied post-MMA (f16x2 domain)
#define SSCALE (0.015625f * 1.44269504088896340736f)

// ---- prep: K,V -> f16x2 fragment-major tile blocks (m16n8k16 layouts) ----
// grid = NTILE*4. K: one float4/thread. V (tid<128): key-pair packs.
// (exact layout/structure of the 39.4us kernel)
__global__ __launch_bounds__(256)
void prep_kv(const float* __restrict__ k, const float* __restrict__ v) {
    const int tile = blockIdx.x >> 2;
    const int quad = blockIdx.x & 3;
    const int tid  = threadIdx.x;
    const float4* kg = (const float4*)(k + (size_t)tile * KT * DKE);
    const float4* vg = (const float4*)(v + (size_t)tile * KT * DKE);
    uint32_t* kd = g_kh[tile];
    uint32_t* vd = g_vh[tile];

    // --- K quarter ---
    {
        int idx = quad * 256 + tid;       // float4 index 0..1023
        int r   = idx >> 4;               // key row in tile
        int c0  = (idx & 15) << 2;        // dim base (aligned 4)
        float4 x = kg[idx];
        int nb  = r >> 3, gg = r & 7;
        int k16 = c0 >> 4, k16p = k16 >> 1;
        int b   = (c0 >> 3) & 1;
        int w   = 2 * (k16 & 1) + b;
        int t0  = (c0 & 7) >> 1;          // 0 or 2
        uint32_t* base = kd + ((nb * 2 + k16p) * 32 + gg * 4) * 4;
        base[t0 * 4 + w]       = f16x2(x.y, x.x);
        base[(t0 + 1) * 4 + w] = f16x2(x.w, x.z);
    }

    // --- V quarter (key-pair items, tid<128) ---
    if (tid < 128) {
        int pi = quad * 128 + tid;        // pair index 0..511
        int r0 = (pi >> 4) * 2;           // even key
        int c0 = (pi & 15) * 4;           // dim base
        float4 v0 = vg[r0 * (DKE / 4) + (c0 >> 2)];
        float4 v1 = vg[(r0 + 1) * (DKE / 4) + (c0 >> 2)];
        int k16 = r0 >> 4;
        int p16 = r0 & 15;
        int b   = p16 >> 3;
        int tt  = (p16 & 7) >> 1;
        int nb  = c0 >> 3, nbp = nb >> 1;
        int w   = b + 2 * (nb & 1);
        int g0  = c0 & 7;
        uint32_t* base = vd + ((k16 * 4 + nbp) * 32) * 4;
        base[(g0 + 0) * 16 + tt * 4 + w] = f16x2(v1.x, v0.x);
        base[(g0 + 1) * 16 + tt * 4 + w] = f16x2(v1.y, v0.y);
        base[(g0 + 2) * 16 + tt * 4 + w] = f16x2(v1.z, v0.z);
        base[(g0 + 3) * 16 + tt * 4 + w] = f16x2(v1.w, v0.w);
    }
}

__global__ __launch_bounds__(256, 2)
void attn_phase1(const float* __restrict__ q) {
    const int m = blockIdx.y;
    const int c = blockIdx.x;
    if (c > m / CPT) return;

    __shared__ uint32_t ksf[2][TWK];       // 16 KB, K double buffer
    __shared__ uint32_t vsf[TWV];          //  8 KB, V single buffer
    __shared__ __align__(8) uint64_t mb[3];   // mbK[0], mbK[1], mbV

    const int tid  = threadIdx.x;
    const int w    = tid >> 5;
    const int lane = tid & 31;
    const int g    = lane >> 2;
    const int t    = lane & 3;
    const int row_base = m * QT + w * WROWS;
    const int row0 = row_base + g;
    const int row1 = row0 + 8;

    const uint32_t ksb  = (uint32_t)__cvta_generic_to_shared(&ksf[0][0]);
    const uint32_t vsb  = (uint32_t)__cvta_generic_to_shared(vsf);
    const uint32_t mbb  = (uint32_t)__cvta_generic_to_shared(mb);

    const int kstart = c * CHUNK;
    const int kend   = min(kstart + CHUNK, (m + 1) * QT);
    const int ntiles = (kend - kstart) / KT;
    const int tile0  = kstart / KT;

    // ---- init mbarriers, then launch K(0) bulk while building Q frags ----
    if (tid == 0) {
        mbar_init(mbb,      1);
        mbar_init(mbb + 8,  1);
        mbar_init(mbb + 16, 1);
    }
    __syncthreads();
    if (tid == 0) {
        mbar_expect(mbb, TILEB);
        bulk_cp(ksb, g_kh[tile0], TILEB, mbb);
    }

    // ---- Q fragments (raw fp16; scale applied post-MMA) ----
    uint32_t qA[4][4];
    #pragma unroll
    for (int k16 = 0; k16 < 4; k16++) {
        const float* q0 = q + (size_t)row0 * DKE + k16 * 16;
        const float* q1 = q + (size_t)row1 * DKE + k16 * 16;
        qA[k16][0] = f16x2(q0[2 * t + 1], q0[2 * t]);
        qA[k16][1] = f16x2(q1[2 * t + 1], q1[2 * t]);
        qA[k16][2] = f16x2(q0[2 * t + 9], q0[2 * t + 8]);
        qA[k16][3] = f16x2(q1[2 * t + 9], q1[2 * t + 8]);
    }

    const uint32_t sc2  = f16x2(SSCALE, SSCALE);
    const uint32_t ones = (g == 0) ? 0x3C003C00u : 0u;   // ones-column B frag

    float o[8][4];
    #pragma unroll
    for (int nb = 0; nb < 8; nb++)
        o[nb][0] = o[nb][1] = o[nb][2] = o[nb][3] = 0.f;
    float ol[4] = {0.f, 0.f, 0.f, 0.f};   // l accumulator (tensor-core sum)

    uint32_t pP[8][2];   // packed p

    for (int i = 0; i < ntiles; i++) {
        __syncthreads();   // WAR: all warps done with vsf and ksf[(i+1)&1]

        if (tid == 0) {
            // V(i): consumed after the V-wait below (QK window to land)
            mbar_expect(mbb + 16, TILEB);
            bulk_cp(vsb, g_vh[tile0 + i], TILEB, mbb + 16);
            // K(i+1): whole-tile window
            if (i + 1 < ntiles) {
                uint32_t mk = mbb + 8 * ((i + 1) & 1);
                mbar_expect(mk, TILEB);
                bulk_cp(ksb + ((i + 1) & 1) * TILEB, g_kh[tile0 + i + 1], TILEB, mk);
            }
        }

        // wait K(i): barrier (i&1), completion number i/2 -> parity (i>>1)&1
        mbar_wait(mbb + 8 * (i & 1), (i >> 1) & 1);

        const int kt = kstart + i * KT;
        const bool active = (kt <= row_base + WROWS - 1);  // warp-uniform
        const uint32_t* kbuf = ksf[i & 1];

        if (active) {
            // ---- S = Q K^T (fp16 m16n8k16, fp32 accum) ----
            float s[8][4];
            #pragma unroll
            for (int nb = 0; nb < 8; nb++)
                s[nb][0] = s[nb][1] = s[nb][2] = s[nb][3] = 0.f;
            #pragma unroll
            for (int nb = 0; nb < 8; nb++) {
                #pragma unroll
                for (int kp = 0; kp < 2; kp++) {
                    uint4 b = *(const uint4*)&kbuf[((nb * 2 + kp) * 32 + lane) * 4];
                    mma_f16(s[nb], qA[2 * kp],     b.x, b.y);
                    mma_f16(s[nb], qA[2 * kp + 1], b.z, b.w);
                }
            }

            // ---- mask (fp32) + packed f16x2 softmax: p = 2^(s*SC) ----
            const bool diag = (kt + KT - 1 > row_base);
            #pragma unroll
            for (int nb = 0; nb < 8; nb++) {
                float t0 = s[nb][0], t1 = s[nb][1];
                float t2 = s[nb][2], t3 = s[nb][3];
                if (diag) {
                    int j0 = kt + nb * 8 + 2 * t;
                    int j1 = j0 + 1;
                    if (j0 > row0) t0 = -1e30f;   // -> f16 -inf -> p = 0
                    if (j1 > row0) t1 = -1e30f;
                    if (j0 > row1) t2 = -1e30f;
                    if (j1 > row1) t3 = -1e30f;
                }
                pP[nb][0] = hex2(hmul2(f16x2(t1, t0), sc2));
                pP[nb][1] = hex2(hmul2(f16x2(t3, t2), sc2));
            }
        }

        // wait V(i): completes once per tile -> parity i&1
        mbar_wait(mbb + 16, i & 1);

        if (active) {
            // ---- O += P V ; l += P * ones (constant-register B frag) ----
            #pragma unroll
            for (int k16 = 0; k16 < 4; k16++) {
                uint32_t pA[4];
                pA[0] = pP[2 * k16][0];
                pA[1] = pP[2 * k16][1];
                pA[2] = pP[2 * k16 + 1][0];
                pA[3] = pP[2 * k16 + 1][1];
                #pragma unroll
                for (int nbp = 0; nbp < 4; nbp++) {
                    uint4 b = *(const uint4*)&vsf[((k16 * 4 + nbp) * 32 + lane) * 4];
                    mma_f16(o[2 * nbp],     pA, b.x, b.y);
                    mma_f16(o[2 * nbp + 1], pA, b.z, b.w);
                }
                mma_f16(ol, pA, ones, ones);   // col 0 = row sum of p
            }
        }
    }

    // ---- write split-K partials (l lives in t==0's col-0 accumulators) ----
    #pragma unroll
    for (int nb = 0; nb < 8; nb++) {
        *(float2*)&g_pout[c][row0][nb * 8 + 2 * t] = make_float2(o[nb][0], o[nb][1]);
        *(float2*)&g_pout[c][row1][nb * 8 + 2 * t] = make_float2(o[nb][2], o[nb][3]);
    }
    if (t == 0) {
        g_pl[c][row0] = ol[0];
        g_pl[c][row1] = ol[2];
    }
}

// Combine: one warp per row; loads predicated on the row's active chunk count.
// (exact 39.4us version)
__global__ __launch_bounds__(256)
void attn_phase2(float* __restrict__ out) {
    const int row  = blockIdx.x * 8 + (threadIdx.x >> 5);
    const int lane = threadIdx.x & 31;
    const int nch  = row / CHUNK + 1;

    float denom = 0.f, o0 = 0.f, o1 = 0.f;
    #pragma unroll
    for (int c = 0; c < MAXC; c++) {
        if (c < nch) {
            denom += g_pl[c][row];
            o0 += g_pout[c][row][lane];
            o1 += g_pout[c][row][lane + 32];
        }
    }
    float inv = 1.0f / denom;
    out[(size_t)row * DKE + lane]      = o0 * inv;
    out[(size_t)row * DKE + lane + 32] = o1 * inv;
}

extern "C" void kernel_launch(void* const* d_in, const int* in_sizes, int n_in,
                              void* d_out, int out_size) {
    const float* q = (const float*)d_in[0];
    const float* k = (const float*)d_in[1];
    const float* v = (const float*)d_in[2];
    float* out = (float*)d_out;

    prep_kv<<<NTILE * 4, 256>>>(k, v);
    dim3 grid1(MAXC, NQT);
    attn_phase1<<<grid1, 256>>>(q);
    attn_phase2<<<SEQ / 8, 256>>>(out);
}

// round 15
// speedup vs baseline: 1.5335x; 1.0322x over previous
#include <cuda_runtime.h>
#include <stdint.h>

#define SEQ   8192
#define DKE   64
#define QT    128          // query rows per CTA
#define KT    64           // keys per tile
#define CHUNK 1024         // keys per split-K chunk
#define NQT   (SEQ/QT)     // 64
#define MAXC  (SEQ/CHUNK)  // 8
#define CPT   (CHUNK/QT)   // 8
#define WROWS 16           // q rows per warp
#define NTILE (SEQ/KT)     // 128 key tiles
#define TWT   4096         // uint32 words per fused K+V tile block
#define TILEB (TWT*4)      // 16384 bytes per fused tile

// scratch (__device__ globals; no allocation). Zero-init (.bss) at load.
__device__ float    g_pout[MAXC][SEQ][DKE];  // unnormalized partial O
__device__ float    g_pl[MAXC][SEQ];         // partial row sum
__device__ uint32_t g_kv[NTILE][TWT];        // fused tiles: K block | V block

__device__ __forceinline__ uint32_t f16x2(float hi, float lo) {
    uint32_t r;
    asm("cvt.rn.f16x2.f32 %0, %1, %2;" : "=r"(r) : "f"(hi), "f"(lo));
    return r;
}
__device__ __forceinline__ uint32_t hmul2(uint32_t a, uint32_t b) {
    uint32_t r;
    asm("mul.f16x2 %0, %1, %2;" : "=r"(r) : "r"(a), "r"(b));
    return r;
}
__device__ __forceinline__ uint32_t hex2(uint32_t a) {
    uint32_t r;
    asm("ex2.approx.f16x2 %0, %1;" : "=r"(r) : "r"(a));
    return r;
}
__device__ __forceinline__ void mma_f16(float c[4], const uint32_t a[4],
                                        uint32_t b0, uint32_t b1) {
    asm("mma.sync.aligned.m16n8k16.row.col.f32.f16.f16.f32 "
        "{%0,%1,%2,%3}, {%4,%5,%6,%7}, {%8,%9}, {%0,%1,%2,%3};"
        : "+f"(c[0]), "+f"(c[1]), "+f"(c[2]), "+f"(c[3])
        : "r"(a[0]), "r"(a[1]), "r"(a[2]), "r"(a[3]), "r"(b0), "r"(b1));
}
// ---- bulk async copy (TMA/UBLKCP) + mbarrier ----
__device__ __forceinline__ void mbar_init(uint32_t addr, uint32_t count) {
    asm volatile("mbarrier.init.shared.b64 [%0], %1;" :: "r"(addr), "r"(count) : "memory");
}
__device__ __forceinline__ void mbar_expect(uint32_t addr, uint32_t bytes) {
    asm volatile("mbarrier.arrive.expect_tx.shared.b64 _, [%0], %1;"
                 :: "r"(addr), "r"(bytes) : "memory");
}
__device__ __forceinline__ void mbar_wait(uint32_t addr, uint32_t parity) {
    asm volatile(
        "{\n\t.reg .pred P;\n\t"
        "W_%=:\n\t"
        "mbarrier.try_wait.parity.acquire.cta.shared::cta.b64 P, [%0], %1, 0x989680;\n\t"
        "@!P bra W_%=;\n\t}"
        :: "r"(addr), "r"(parity) : "memory");
}
__device__ __forceinline__ void bulk_cp(uint32_t sdst, const void* gsrc,
                                        uint32_t bytes, uint32_t mbar) {
    asm volatile(
        "cp.async.bulk.shared::cta.global.mbarrier::complete_tx::bytes [%0], [%1], %2, [%3];"
        :: "r"(sdst), "l"(gsrc), "r"(bytes), "r"(mbar) : "memory");
}

// score scale: 1/64 (problem scale) * log2(e), applied post-MMA (f16x2 domain)
#define SSCALE (0.015625f * 1.44269504088896340736f)

// ---- prep: K,V -> f16x2 fragment-major blocks, fused per tile ----
// grid = NTILE*4. K: one float4/thread. V (tid<128): key-pair packs.
__global__ __launch_bounds__(256)
void prep_kv(const float* __restrict__ k, const float* __restrict__ v) {
    const int tile = blockIdx.x >> 2;
    const int quad = blockIdx.x & 3;
    const int tid  = threadIdx.x;
    const float4* kg = (const float4*)(k + (size_t)tile * KT * DKE);
    const float4* vg = (const float4*)(v + (size_t)tile * KT * DKE);
    uint32_t* kd = g_kv[tile];
    uint32_t* vd = g_kv[tile] + 2048;

    // --- K quarter ---
    {
        int idx = quad * 256 + tid;       // float4 index 0..1023
        int r   = idx >> 4;               // key row in tile
        int c0  = (idx & 15) << 2;        // dim base (aligned 4)
        float4 x = kg[idx];
        int nb  = r >> 3, gg = r & 7;
        int k16 = c0 >> 4, k16p = k16 >> 1;
        int b   = (c0 >> 3) & 1;
        int w   = 2 * (k16 & 1) + b;
        int t0  = (c0 & 7) >> 1;          // 0 or 2
        uint32_t* base = kd + ((nb * 2 + k16p) * 32 + gg * 4) * 4;
        base[t0 * 4 + w]       = f16x2(x.y, x.x);
        base[(t0 + 1) * 4 + w] = f16x2(x.w, x.z);
    }

    // --- V quarter (key-pair items, tid<128) ---
    if (tid < 128) {
        int pi = quad * 128 + tid;        // pair index 0..511
        int r0 = (pi >> 4) * 2;           // even key
        int c0 = (pi & 15) * 4;           // dim base
        float4 v0 = vg[r0 * (DKE / 4) + (c0 >> 2)];
        float4 v1 = vg[(r0 + 1) * (DKE / 4) + (c0 >> 2)];
        int k16 = r0 >> 4;
        int p16 = r0 & 15;
        int b   = p16 >> 3;
        int tt  = (p16 & 7) >> 1;
        int nb  = c0 >> 3, nbp = nb >> 1;
        int w   = b + 2 * (nb & 1);
        int g0  = c0 & 7;
        uint32_t* base = vd + ((k16 * 4 + nbp) * 32) * 4;
        base[(g0 + 0) * 16 + tt * 4 + w] = f16x2(v1.x, v0.x);
        base[(g0 + 1) * 16 + tt * 4 + w] = f16x2(v1.y, v0.y);
        base[(g0 + 2) * 16 + tt * 4 + w] = f16x2(v1.z, v0.z);
        base[(g0 + 3) * 16 + tt * 4 + w] = f16x2(v1.w, v0.w);
    }
}

__global__ __launch_bounds__(256, 2)
void attn_phase1(const float* __restrict__ q) {
    const int m = blockIdx.y;
    const int c = blockIdx.x;
    if (c > m / CPT) return;

    __shared__ uint32_t kvsf[2][TWT];        // 32 KB, fused K|V double buffer
    __shared__ __align__(8) uint64_t mb[2];  // one mbarrier per buffer

    const int tid  = threadIdx.x;
    const int w    = tid >> 5;
    const int lane = tid & 31;
    const int g    = lane >> 2;
    const int t    = lane & 3;
    const int row_base = m * QT + w * WROWS;
    const int row0 = row_base + g;
    const int row1 = row0 + 8;

    const uint32_t kvb = (uint32_t)__cvta_generic_to_shared(&kvsf[0][0]);
    const uint32_t mbb = (uint32_t)__cvta_generic_to_shared(mb);

    const int kstart = c * CHUNK;
    const int kend   = min(kstart + CHUNK, (m + 1) * QT);
    const int ntiles = (kend - kstart) / KT;
    const int tile0  = kstart / KT;

    // ---- init mbarriers, launch tile0 bulk while building Q frags ----
    if (tid == 0) {
        mbar_init(mbb,     1);
        mbar_init(mbb + 8, 1);
    }
    __syncthreads();
    if (tid == 0) {
        mbar_expect(mbb, TILEB);
        bulk_cp(kvb, g_kv[tile0], TILEB, mbb);
    }

    // ---- Q fragments (raw fp16; scale applied post-MMA) ----
    uint32_t qA[4][4];
    #pragma unroll
    for (int k16 = 0; k16 < 4; k16++) {
        const float* q0 = q + (size_t)row0 * DKE + k16 * 16;
        const float* q1 = q + (size_t)row1 * DKE + k16 * 16;
        qA[k16][0] = f16x2(q0[2 * t + 1], q0[2 * t]);
        qA[k16][1] = f16x2(q1[2 * t + 1], q1[2 * t]);
        qA[k16][2] = f16x2(q0[2 * t + 9], q0[2 * t + 8]);
        qA[k16][3] = f16x2(q1[2 * t + 9], q1[2 * t + 8]);
    }

    const uint32_t sc2  = f16x2(SSCALE, SSCALE);
    const uint32_t ones = (g == 0) ? 0x3C003C00u : 0u;   // ones-column B frag

    float o[8][4];
    #pragma unroll
    for (int nb = 0; nb < 8; nb++)
        o[nb][0] = o[nb][1] = o[nb][2] = o[nb][3] = 0.f;
    float ol[4] = {0.f, 0.f, 0.f, 0.f};   // l accumulator (tensor-core sum)

    uint32_t pP[8][2];   // packed p

    for (int i = 0; i < ntiles; i++) {
        __syncthreads();   // WAR: all warps done with buffer (i+1)&1 (tile i-1)

        if (tid == 0 && i + 1 < ntiles) {
            uint32_t mk = mbb + 8 * ((i + 1) & 1);
            mbar_expect(mk, TILEB);
            bulk_cp(kvb + ((i + 1) & 1) * TILEB, g_kv[tile0 + i + 1], TILEB, mk);
        }

        // wait tile i: barrier (i&1), completion i/2 -> parity (i>>1)&1
        mbar_wait(mbb + 8 * (i & 1), (i >> 1) & 1);

        const int kt = kstart + i * KT;
        const bool active = (kt <= row_base + WROWS - 1);  // warp-uniform
        const uint32_t* kbuf = kvsf[i & 1];
        const uint32_t* vbuf = kbuf + 2048;

        if (active) {
            // ---- S = Q K^T (fp16 m16n8k16, fp32 accum) ----
            float s[8][4];
            #pragma unroll
            for (int nb = 0; nb < 8; nb++)
                s[nb][0] = s[nb][1] = s[nb][2] = s[nb][3] = 0.f;
            #pragma unroll
            for (int nb = 0; nb < 8; nb++) {
                #pragma unroll
                for (int kp = 0; kp < 2; kp++) {
                    uint4 b = *(const uint4*)&kbuf[((nb * 2 + kp) * 32 + lane) * 4];
                    mma_f16(s[nb], qA[2 * kp],     b.x, b.y);
                    mma_f16(s[nb], qA[2 * kp + 1], b.z, b.w);
                }
            }

            // ---- mask (fp32) + packed f16x2 softmax: p = 2^(s*SC) ----
            const bool diag = (kt + KT - 1 > row_base);
            #pragma unroll
            for (int nb = 0; nb < 8; nb++) {
                float t0 = s[nb][0], t1 = s[nb][1];
                float t2 = s[nb][2], t3 = s[nb][3];
                if (diag) {
                    int j0 = kt + nb * 8 + 2 * t;
                    int j1 = j0 + 1;
                    if (j0 > row0) t0 = -1e30f;   // -> f16 -inf -> p = 0
                    if (j1 > row0) t1 = -1e30f;
                    if (j0 > row1) t2 = -1e30f;
                    if (j1 > row1) t3 = -1e30f;
                }
                pP[nb][0] = hex2(hmul2(f16x2(t1, t0), sc2));
                pP[nb][1] = hex2(hmul2(f16x2(t3, t2), sc2));
            }

            // ---- O += P V ; l += P * ones (no mid-tile wait: V came with K) ----
            #pragma unroll
            for (int k16 = 0; k16 < 4; k16++) {
                uint32_t pA[4];
                pA[0] = pP[2 * k16][0];
                pA[1] = pP[2 * k16][1];
                pA[2] = pP[2 * k16 + 1][0];
                pA[3] = pP[2 * k16 + 1][1];
                #pragma unroll
                for (int nbp = 0; nbp < 4; nbp++) {
                    uint4 b = *(const uint4*)&vbuf[((k16 * 4 + nbp) * 32 + lane) * 4];
                    mma_f16(o[2 * nbp],     pA, b.x, b.y);
                    mma_f16(o[2 * nbp + 1], pA, b.z, b.w);
                }
                mma_f16(ol, pA, ones, ones);   // col 0 = row sum of p
            }
        }
    }

    // ---- write split-K partials (l lives in t==0's col-0 accumulators) ----
    #pragma unroll
    for (int nb = 0; nb < 8; nb++) {
        *(float2*)&g_pout[c][row0][nb * 8 + 2 * t] = make_float2(o[nb][0], o[nb][1]);
        *(float2*)&g_pout[c][row1][nb * 8 + 2 * t] = make_float2(o[nb][2], o[nb][3]);
    }
    if (t == 0) {
        g_pl[c][row0] = ol[0];
        g_pl[c][row1] = ol[2];
    }
}

// Combine: one warp per row; loads predicated on the row's active chunk count.
__global__ __launch_bounds__(256)
void attn_phase2(float* __restrict__ out) {
    const int row  = blockIdx.x * 8 + (threadIdx.x >> 5);
    const int lane = threadIdx.x & 31;
    const int nch  = row / CHUNK + 1;

    float denom = 0.f, o0 = 0.f, o1 = 0.f;
    #pragma unroll
    for (int c = 0; c < MAXC; c++) {
        if (c < nch) {
            denom += g_pl[c][row];
            o0 += g_pout[c][row][lane];
            o1 += g_pout[c][row][lane + 32];
        }
    }
    float inv = 1.0f / denom;
    out[(size_t)row * DKE + lane]      = o0 * inv;
    out[(size_t)row * DKE + lane + 32] = o1 * inv;
}

extern "C" void kernel_launch(void* const* d_in, const int* in_sizes, int n_in,
                              void* d_out, int out_size) {
    const float* q = (const float*)d_in[0];
    const float* k = (const float*)d_in[1];
    const float* v = (const float*)d_in[2];
    float* out = (float*)d_out;

    prep_kv<<<NTILE * 4, 256>>>(k, v);
    dim3 grid1(MAXC, NQT);
    attn_phase1<<<grid1, 256>>>(q);
    attn_phase2<<<SEQ / 8, 256>>>(out);
}